// round 3
// baseline (speedup 1.0000x reference)
#include <cuda_runtime.h>
#include <cstdint>

#define B_   4096
#define T_   1024
#define H_   64
#define G_   192      // 3*H
#define NB   148      // blocks = SMs
#define NW   8        // warps per block
#define RPW  7        // rows per warp (1184*7 = 8288 >= 8192)
#define NROW 8192     // 2*B_

// Final hidden states, row-major: row rho in [0,8192), rho = seq*B_ + batch
__device__ float g_hlast[NROW * H_];

// ---- packed f32x2 FMA ----
__device__ __forceinline__ unsigned long long ffma2(unsigned long long a,
                                                    unsigned long long b,
                                                    unsigned long long c) {
    unsigned long long d;
    asm("fma.rn.f32x2 %0, %1, %2, %3;" : "=l"(d) : "l"(a), "l"(b), "l"(c));
    return d;
}
__device__ __forceinline__ float pair_sum(unsigned long long v) {
    float lo, hi;
    asm("mov.b64 {%0, %1}, %2;" : "=f"(lo), "=f"(hi) : "l"(v));
    return lo + hi;
}

// ---- fast sigmoid/tanh (ex2.approx + rcp.approx, ~2 ulp) ----
__device__ __forceinline__ float ex2f(float x) { float r; asm("ex2.approx.f32 %0, %1;" : "=f"(r) : "f"(x)); return r; }
__device__ __forceinline__ float rcpf(float x) { float r; asm("rcp.approx.f32 %0, %1;" : "=f"(r) : "f"(x)); return r; }
__device__ __forceinline__ float sigm(float x) {
    return rcpf(1.0f + ex2f(-1.4426950408889634f * x));
}
__device__ __forceinline__ float tanh_(float x) {
    return fmaf(2.0f, sigm(2.0f * x), -1.0f);
}

// ============================================================================
// GRU: 148 blocks x 8 warps; each warp owns 7 rows (row = r*1184 + warp_id).
// W_hh in smem as float2 K-pairs: Wp[k2][j] = {W[j][2k2], W[j][2k2+1]}.
// Single pass over all 6 gate columns; h broadcast via LDS.128 (2 K-pairs).
// ============================================================================
__global__ __launch_bounds__(256)
void gru_kernel(const float* __restrict__ x1, const float* __restrict__ x2,
                const float* __restrict__ Wih, const float* __restrict__ Whh,
                const float* __restrict__ bih, const float* __restrict__ bhh)
{
    extern __shared__ float smem[];
    float2* Wp = reinterpret_cast<float2*>(smem);      // [32][192] float2 = 48 KB
    float*  hb = smem + 2 * 32 * G_;                   // [NW][RPW][64] = 14 KB

    const int tid = threadIdx.x;
    const int w   = tid >> 5;
    const int l   = tid & 31;

    // Stage W_hh as K-pairs
    for (int i = tid; i < 32 * G_; i += 256) {
        int k2 = i / G_, j = i % G_;
        Wp[i] = make_float2(Whh[j * H_ + 2 * k2], Whh[j * H_ + 2 * k2 + 1]);
    }
    // h0 = 0
    for (int i = tid; i < NW * RPW * H_; i += 256) hb[i] = 0.0f;

    // Per-lane gate-column constants: lane owns j = l + 32*g, g = 0..5
    float wi0[6], wi1[6], wi2[6], bi[6], bh[6];
#pragma unroll
    for (int g = 0; g < 6; g++) {
        int j = l + 32 * g;
        wi0[g] = Wih[j * 3 + 0];
        wi1[g] = Wih[j * 3 + 1];
        wi2[g] = Wih[j * 3 + 2];
        bi[g]  = bih[j];
        bh[g]  = bhh[j];
    }

    const int wg = blockIdx.x * NW + w;     // global warp id, 0..1183

    // x fetch: lanes 0..20 each own one (row r, component c)
    const float* xp = nullptr;
    if (l < 3 * RPW) {
        int rr = l / 3, c = l % 3;
        int rho = rr * (NB * NW) + wg;
        if (rho >= NROW) rho = NROW - 1;    // dummy rows read row 8191 (harmless)
        const float* base = (rho < B_) ? (x1 + (size_t)rho * T_ * 3)
                                       : (x2 + (size_t)(rho - B_) * T_ * 3);
        xp = base + c;
    }

    float hlo[RPW], hhi[RPW];
#pragma unroll
    for (int r = 0; r < RPW; r++) { hlo[r] = 0.0f; hhi[r] = 0.0f; }

    float* hbw = hb + w * RPW * H_;
    const ulonglong2* hrow4 = reinterpret_cast<const ulonglong2*>(hbw);

    __syncthreads();

    for (int t = 0; t < T_; t++) {
        float xv = (l < 3 * RPW) ? __ldg(xp) : 0.0f;
        xp += 3;

        unsigned long long acc[RPW][6];
#pragma unroll
        for (int r = 0; r < RPW; r++)
#pragma unroll
            for (int g = 0; g < 6; g++) acc[r][g] = 0ull;

        // K loop: k4 covers K-pairs 2k4 and 2k4+1 (4 scalar K per iter)
#pragma unroll 4
        for (int k4 = 0; k4 < 16; k4++) {
            const unsigned long long* pa =
                reinterpret_cast<const unsigned long long*>(Wp + (2 * k4) * G_ + l);
            const unsigned long long* pb = pa + G_;
            unsigned long long wa[6], wb[6];
#pragma unroll
            for (int g = 0; g < 6; g++) { wa[g] = pa[32 * g]; wb[g] = pb[32 * g]; }
#pragma unroll
            for (int r = 0; r < RPW; r++) {
                ulonglong2 hv = hrow4[r * 16 + k4];   // 16B broadcast
#pragma unroll
                for (int g = 0; g < 6; g++) {
                    acc[r][g] = ffma2(hv.x, wa[g], acc[r][g]);
                    acc[r][g] = ffma2(hv.y, wb[g], acc[r][g]);
                }
            }
        }

        __syncwarp();   // all lanes done reading h

#pragma unroll
        for (int r = 0; r < RPW; r++) {
            float x0  = __shfl_sync(0xffffffffu, xv, r * 3 + 0);
            float x1v = __shfl_sync(0xffffffffu, xv, r * 3 + 1);
            float x2v = __shfl_sync(0xffffffffu, xv, r * 3 + 2);

            float ax[6], aa[6];
#pragma unroll
            for (int g = 0; g < 6; g++) {
                ax[g] = fmaf(x2v, wi2[g], fmaf(x1v, wi1[g], fmaf(x0, wi0[g], bi[g])));
                aa[g] = pair_sum(acc[r][g]) + bh[g];
            }
            // gate order (r, z, n); lane covers j = l (lo) and j = l+32 (hi)
            float rg0 = sigm(aa[0] + ax[0]);
            float rg1 = sigm(aa[1] + ax[1]);
            float zg0 = sigm(aa[2] + ax[2]);
            float zg1 = sigm(aa[3] + ax[3]);
            float ng0 = tanh_(fmaf(rg0, aa[4], ax[4]));
            float ng1 = tanh_(fmaf(rg1, aa[5], ax[5]));

            hlo[r] = fmaf(zg0, hlo[r] - ng0, ng0);   // (1-z)*n + z*h
            hhi[r] = fmaf(zg1, hhi[r] - ng1, ng1);

            hbw[r * H_ + l]      = hlo[r];
            hbw[r * H_ + l + 32] = hhi[r];
        }
        __syncwarp();   // stores visible before next step's broadcasts
    }

    // Final hidden states (skip dummy rows)
#pragma unroll
    for (int r = 0; r < RPW; r++) {
        int rho = r * (NB * NW) + wg;
        if (rho < NROW) {
            g_hlast[rho * H_ + l]      = hlo[r];
            g_hlast[rho * H_ + l + 32] = hhi[r];
        }
    }
}

// ============================================================================
// Head: out[b] = sigmoid(W2 @ relu(W1 @ |h1-h2| + b1) + b2)
// ============================================================================
__global__ void head_kernel(const float* __restrict__ W1, const float* __restrict__ b1,
                            const float* __restrict__ W2, const float* __restrict__ b2,
                            float* __restrict__ out)
{
    __shared__ float w1s[32 * 65];
    __shared__ float diffs[64];

    const int b = blockIdx.x;
    const int l = threadIdx.x;

    for (int i = l; i < 32 * 64; i += 32) {
        int m = i >> 6, k = i & 63;
        w1s[m * 65 + k] = W1[i];
    }
    diffs[l]      = fabsf(g_hlast[b * H_ + l]      - g_hlast[(B_ + b) * H_ + l]);
    diffs[32 + l] = fabsf(g_hlast[b * H_ + 32 + l] - g_hlast[(B_ + b) * H_ + 32 + l]);
    __syncwarp();

    float acc = b1[l];
#pragma unroll
    for (int k = 0; k < 64; k++) acc = fmaf(w1s[l * 65 + k], diffs[k], acc);
    acc = fmaxf(acc, 0.0f) * W2[l];

#pragma unroll
    for (int o = 16; o > 0; o >>= 1) acc += __shfl_xor_sync(0xffffffffu, acc, o);
    if (l == 0) out[b] = sigm(acc + b2[0]);
}

// ============================================================================
extern "C" void kernel_launch(void* const* d_in, const int* in_sizes, int n_in,
                              void* d_out, int out_size)
{
    (void)in_sizes; (void)n_in; (void)out_size;
    const float* x1  = (const float*)d_in[0];
    const float* x2  = (const float*)d_in[1];
    const float* Wih = (const float*)d_in[2];
    const float* Whh = (const float*)d_in[3];
    const float* bih = (const float*)d_in[4];
    const float* bhh = (const float*)d_in[5];
    const float* W1  = (const float*)d_in[6];
    const float* b1  = (const float*)d_in[7];
    const float* W2  = (const float*)d_in[8];
    const float* b2  = (const float*)d_in[9];
    float* out = (float*)d_out;

    const int dyn_smem = 2 * 32 * G_ * 4 + NW * RPW * H_ * 4;  // 48K + 14K
    cudaFuncSetAttribute(gru_kernel, cudaFuncAttributeMaxDynamicSharedMemorySize, dyn_smem);

    gru_kernel<<<NB, 32 * NW, dyn_smem>>>(x1, x2, Wih, Whh, bih, bhh);
    head_kernel<<<B_, 32>>>(W1, b1, W2, b2, out);
}

// round 4
// speedup vs baseline: 2.0961x; 2.0961x over previous
#include <cuda_runtime.h>
#include <cstdint>

#define B_    4096
#define T_    1024
#define NCTA  128
#define ROWS  64      // rows per CTA (128*64 = 8192 = 2*B_)
#define RS    38      // float2 row stride in hs/Bs (36 data + 2 pad, conflict-free)

__device__ float g_hlast[8192 * 64];

__device__ __forceinline__ uint32_t f2tf(float x) {
    uint32_t r; asm("cvt.rna.tf32.f32 %0, %1;" : "=r"(r) : "f"(x)); return r;
}
__device__ __forceinline__ float tanh_a(float x) {
    float r; asm("tanh.approx.f32 %0, %1;" : "=f"(r) : "f"(x)); return r;
}
__device__ __forceinline__ float sigm(float x) { return fmaf(tanh_a(0.5f * x), 0.5f, 0.5f); }

__device__ __forceinline__ void mma8(float d[4], uint32_t a0, uint32_t a1, uint32_t a2,
                                     uint32_t a3, uint32_t b0, uint32_t b1) {
    asm volatile("mma.sync.aligned.m16n8k8.row.col.f32.tf32.tf32.f32 "
                 "{%0,%1,%2,%3}, {%4,%5,%6,%7}, {%8,%9}, {%0,%1,%2,%3};"
                 : "+f"(d[0]), "+f"(d[1]), "+f"(d[2]), "+f"(d[3])
                 : "r"(a0), "r"(a1), "r"(a2), "r"(a3), "r"(b0), "r"(b1));
}

// ============================================================================
// GRU via warp mma.sync tf32. CTA = 64 rows, 8 warps:
//   warp w: rg = w&1 (rows 32rg..+31, two m16 blocks), cg = w>>1 (gate cols 16cg..+15)
// K-tiles 0..7 = h (K=64); k-tile 8 = [x0,x1,x2,1,0,0,0,0] folding x + b_ih+b_hh
// into r,z pre-acts (its B rows are zero for the n gate).
// smem pair layout: S[row][kt][s] = {v[8kt+s], v[8kt+s+4]}  (matches tf32 frags)
// ============================================================================
__global__ __launch_bounds__(256, 1)
void gru_kernel(const float* __restrict__ x1, const float* __restrict__ x2,
                const float* __restrict__ Wih, const float* __restrict__ Whh,
                const float* __restrict__ bih, const float* __restrict__ bhh)
{
    extern __shared__ float2 sm2[];
    float2* Bs  = sm2;                 // [192][RS]
    float2* hs  = sm2 + 192 * RS;      // [64][RS]
    float*  hsf = reinterpret_cast<float*>(hs);

    const int tid = threadIdx.x;
    const int w = tid >> 5, l = tid & 31;
    const int rg = w & 1, cg = w >> 1;
    const int gid = l >> 2, tg = l & 3;

    // ---- stage B = [Whh | x-fold tile], tf32-rounded ----
    for (int i = tid; i < 192 * 36; i += 256) {
        int n = i / 36, tt = i % 36, kt = tt >> 2, s = tt & 3;
        float2 v;
        if (kt < 8) {
            v.x = __uint_as_float(f2tf(Whh[n * 64 + kt * 8 + s]));
            v.y = __uint_as_float(f2tf(Whh[n * 64 + kt * 8 + s + 4]));
        } else {
            v.x = 0.0f; v.y = 0.0f;
            if (n < 128) {   // r,z rows only
                float xv = (s < 3) ? Wih[n * 3 + s] : (bih[n] + bhh[n]);
                v.x = __uint_as_float(f2tf(xv));
            }
        }
        Bs[n * RS + tt] = v;
    }
    // ---- h0 = 0 ----
    for (int i = tid; i < ROWS * RS * 2; i += 256) hsf[i] = 0.0f;
    __syncthreads();
    if (tid < ROWS) hs[tid * RS + 35] = make_float2(1.0f, 0.0f);  // the "1" for bias fold

    // ---- per-thread n-gate constants for its 4 hidden cols ----
    float win0[4], win1[4], win2[4], bin[4], bhn[4];
#pragma unroll
    for (int u = 0; u < 4; u++) {
        int p = u >> 1, q = u & 1;
        int j = cg * 16 + p * 8 + tg * 2 + q;
        int nr = 128 + j;
        win0[u] = Wih[nr * 3 + 0]; win1[u] = Wih[nr * 3 + 1]; win2[u] = Wih[nr * 3 + 2];
        bin[u]  = bih[nr];         bhn[u]  = bhh[nr];
    }

    // ---- x stream: threads 0..191 each own one (row, component) ----
    const float* xp = nullptr;
    int xrow = 0, xc = 0;
    if (tid < 3 * ROWS) {
        xrow = tid / 3; xc = tid % 3;
        int rho = blockIdx.x * ROWS + xrow;
        xp = (rho < B_) ? (x1 + (size_t)rho * T_ * 3 + xc)
                        : (x2 + (size_t)(rho - B_) * T_ * 3 + xc);
        float xv = __ldg(xp); xp += 3;   // x(0)
        hs[xrow * RS + 32 + xc] = make_float2(__uint_as_float(f2tf(xv)), 0.0f);
    }
    __syncthreads();

    for (int t = 0; t < T_; t++) {
        float xnext = 0.0f;
        if (tid < 3 * ROWS && t + 1 < T_) { xnext = __ldg(xp); xp += 3; }  // prefetch

        float acc[2][6][4];
#pragma unroll
        for (int rb = 0; rb < 2; rb++)
#pragma unroll
            for (int i = 0; i < 6; i++)
#pragma unroll
                for (int c = 0; c < 4; c++) acc[rb][i][c] = 0.0f;

#pragma unroll
        for (int kt = 0; kt < 9; kt++) {
            uint32_t bx[6], by[6];
#pragma unroll
            for (int ti = 0; ti < 6; ti++) {           // ti = gate*2 + pair
                int g = ti >> 1, p = ti & 1;
                int n = (g * 8 + cg * 2 + p) * 8 + gid;
                float2 bb = Bs[n * RS + kt * 4 + tg];
                bx[ti] = __float_as_uint(bb.x); by[ti] = __float_as_uint(bb.y);
            }
#pragma unroll
            for (int rb = 0; rb < 2; rb++) {
                int br = rg * 32 + rb * 16;
                float2 lo = hs[(br + gid) * RS + kt * 4 + tg];
                float2 hi = hs[(br + gid + 8) * RS + kt * 4 + tg];
                uint32_t a0 = __float_as_uint(lo.x), a1 = __float_as_uint(hi.x);
                uint32_t a2 = __float_as_uint(lo.y), a3 = __float_as_uint(hi.y);
#pragma unroll
                for (int ti = 0; ti < 6; ti++)
                    mma8(acc[rb][ti], a0, a1, a2, a3, bx[ti], by[ti]);
            }
        }

        // ---- gate epilogue: all three gates of a unit live on this thread ----
        float hnew[2][2][4];
#pragma unroll
        for (int rb = 0; rb < 2; rb++) {
#pragma unroll
            for (int rs = 0; rs < 2; rs++) {
                int rowl = rg * 32 + rb * 16 + gid + rs * 8;
                float xv0 = hsf[rowl * 2 * RS + 64 + 0];
                float xv1 = hsf[rowl * 2 * RS + 64 + 2];
                float xv2 = hsf[rowl * 2 * RS + 64 + 4];
#pragma unroll
                for (int u = 0; u < 4; u++) {
                    int p = u >> 1, q = u & 1;
                    int c = rs * 2 + q;
                    float r  = sigm(acc[rb][p][c]);          // has x + biases folded
                    float z  = sigm(acc[rb][2 + p][c]);
                    float hn = acc[rb][4 + p][c] + bhn[u];   // h-part only
                    float xn = fmaf(xv2, win2[u], fmaf(xv1, win1[u], fmaf(xv0, win0[u], bin[u])));
                    float nn = tanh_a(fmaf(r, hn, xn));
                    int j = cg * 16 + p * 8 + tg * 2 + q, jm = j & 7;
                    float hold = hsf[rowl * 2 * RS + (j >> 3) * 8 + (jm & 3) * 2 + (jm >> 2)];
                    hnew[rb][rs][u] = __uint_as_float(f2tf(fmaf(z, hold - nn, nn)));
                }
            }
        }
        __syncthreads();   // everyone done reading hs
#pragma unroll
        for (int rb = 0; rb < 2; rb++)
#pragma unroll
            for (int rs = 0; rs < 2; rs++) {
                int rowl = rg * 32 + rb * 16 + gid + rs * 8;
#pragma unroll
                for (int u = 0; u < 4; u++) {
                    int p = u >> 1, q = u & 1;
                    int j = cg * 16 + p * 8 + tg * 2 + q, jm = j & 7;
                    hsf[rowl * 2 * RS + (j >> 3) * 8 + (jm & 3) * 2 + (jm >> 2)] = hnew[rb][rs][u];
                }
            }
        if (tid < 3 * ROWS && t + 1 < T_)
            hs[xrow * RS + 32 + xc] = make_float2(__uint_as_float(f2tf(xnext)), 0.0f);
        __syncthreads();   // h(t+1), x(t+1) visible
    }

    // ---- emit final hidden states ----
    for (int i = tid; i < ROWS * 64; i += 256) {
        int row = i >> 6, j = i & 63, jm = j & 7;
        g_hlast[((size_t)blockIdx.x * ROWS + row) * 64 + j] =
            hsf[row * 2 * RS + (j >> 3) * 8 + (jm & 3) * 2 + (jm >> 2)];
    }
}

// ============================================================================
// Head: out[b] = sigmoid(W2 @ relu(W1 @ |h1-h2| + b1) + b2)
// ============================================================================
__global__ void head_kernel(const float* __restrict__ W1, const float* __restrict__ b1,
                            const float* __restrict__ W2, const float* __restrict__ b2,
                            float* __restrict__ out)
{
    __shared__ float w1s[32 * 65];
    __shared__ float diffs[64];

    const int b = blockIdx.x;
    const int l = threadIdx.x;

    for (int i = l; i < 32 * 64; i += 32) {
        int m = i >> 6, k = i & 63;
        w1s[m * 65 + k] = W1[i];
    }
    diffs[l]      = fabsf(g_hlast[b * 64 + l]        - g_hlast[(B_ + b) * 64 + l]);
    diffs[32 + l] = fabsf(g_hlast[b * 64 + 32 + l]   - g_hlast[(B_ + b) * 64 + 32 + l]);
    __syncwarp();

    float acc = b1[l];
#pragma unroll
    for (int k = 0; k < 64; k++) acc = fmaf(w1s[l * 65 + k], diffs[k], acc);
    acc = fmaxf(acc, 0.0f) * W2[l];

#pragma unroll
    for (int o = 16; o > 0; o >>= 1) acc += __shfl_xor_sync(0xffffffffu, acc, o);
    if (l == 0) out[b] = sigm(acc + b2[0]);
}

// ============================================================================
extern "C" void kernel_launch(void* const* d_in, const int* in_sizes, int n_in,
                              void* d_out, int out_size)
{
    (void)in_sizes; (void)n_in; (void)out_size;
    const float* x1  = (const float*)d_in[0];
    const float* x2  = (const float*)d_in[1];
    const float* Wih = (const float*)d_in[2];
    const float* Whh = (const float*)d_in[3];
    const float* bih = (const float*)d_in[4];
    const float* bhh = (const float*)d_in[5];
    const float* W1  = (const float*)d_in[6];
    const float* b1  = (const float*)d_in[7];
    const float* W2  = (const float*)d_in[8];
    const float* b2  = (const float*)d_in[9];
    float* out = (float*)d_out;

    const int dyn_smem = (192 + ROWS) * RS * (int)sizeof(float2);  // 77824 B
    cudaFuncSetAttribute(gru_kernel, cudaFuncAttributeMaxDynamicSharedMemorySize, dyn_smem);

    gru_kernel<<<NCTA, 256, dyn_smem>>>(x1, x2, Wih, Whh, bih, bhh);
    head_kernel<<<B_, 32>>>(W1, b1, W2, b2, out);
}

// round 6
// speedup vs baseline: 2.5805x; 1.2311x over previous
#include <cuda_runtime.h>
#include <cstdint>

#define B_    4096
#define T_    1024
#define NCTA  128
#define ROWS  64      // rows per CTA (128*64 = 8192 = 2*B_)
#define RS    36      // float2 per row: stride%16==4 -> conflict-free LDS.64

__device__ float g_hlast[8192 * 64];

__device__ __forceinline__ float tfr(float x) {   // round-to-nearest tf32
    uint32_t r; asm("cvt.rna.tf32.f32 %0, %1;" : "=r"(r) : "f"(x));
    return __uint_as_float(r);
}
__device__ __forceinline__ float tanh_a(float x) {
    float r; asm("tanh.approx.f32 %0, %1;" : "=f"(r) : "f"(x)); return r;
}
__device__ __forceinline__ float sigm(float x) { return fmaf(tanh_a(0.5f * x), 0.5f, 0.5f); }

__device__ __forceinline__ void mma8(float d[4], uint32_t a0, uint32_t a1, uint32_t a2,
                                     uint32_t a3, uint32_t b0, uint32_t b1) {
    asm volatile("mma.sync.aligned.m16n8k8.row.col.f32.tf32.tf32.f32 "
                 "{%0,%1,%2,%3}, {%4,%5,%6,%7}, {%8,%9}, {%0,%1,%2,%3};"
                 : "+f"(d[0]), "+f"(d[1]), "+f"(d[2]), "+f"(d[3])
                 : "r"(a0), "r"(a1), "r"(a2), "r"(a3), "r"(b0), "r"(b1));
}

// ============================================================================
// GRU via mma.sync tf32. 128 CTAs x 512 threads, 16 warps:
//   warp w: rg = w&3 (16 rows), cg = w>>2 (16 cols of each gate)
// K-tiles 0..7 = h (K=64); kt 8 = [x0,x1,x2,1,0,0,0,0] folds x + b_ih+b_hh into
// r,z pre-acts (zero rows for the n gate; its x-part is done on the fma pipe).
// Ping-pong h buffers -> single __syncthreads per step. hold[] in registers.
// smem pair layout: S[row][kt][s] = {v[8kt+s], v[8kt+s+4]}  (tf32 frag layout)
// ============================================================================
__global__ __launch_bounds__(512, 1)
void gru_kernel(const float* __restrict__ x1, const float* __restrict__ x2,
                const float* __restrict__ Wih, const float* __restrict__ Whh,
                const float* __restrict__ bih, const float* __restrict__ bhh)
{
    extern __shared__ float2 sm2[];
    float2* Bs = sm2;                       // [192][RS]
    float2* h0 = sm2 + 192 * RS;            // [64][RS] buffer 0
    float2* h1 = h0 + ROWS * RS;            // [64][RS] buffer 1

    const int tid = threadIdx.x;
    const int w = tid >> 5, l = tid & 31;
    const int rg = w & 3, cg = w >> 2;
    const int gid = l >> 2, tg = l & 3;

    // ---- stage B = [Whh | x-fold tile], tf32-rounded ----
    for (int i = tid; i < 192 * RS; i += 512) {
        int n = i / RS, tt = i % RS, kt = tt >> 2, s = tt & 3;
        float2 v;
        if (kt < 8) {
            v.x = tfr(Whh[n * 64 + kt * 8 + s]);
            v.y = tfr(Whh[n * 64 + kt * 8 + s + 4]);
        } else {
            v.x = 0.0f; v.y = 0.0f;
            if (n < 128)   // r,z rows only
                v.x = tfr((s < 3) ? Wih[n * 3 + s] : (bih[n] + bhh[n]));
        }
        Bs[i] = v;
    }
    // ---- zero both h buffers ----
    {
        float* hz = reinterpret_cast<float*>(h0);
        for (int i = tid; i < 2 * ROWS * RS * 2; i += 512) hz[i] = 0.0f;
    }
    __syncthreads();
    // bias "1" column in BOTH buffers (kt=8, s=3 -> {1, 0})
    if (tid < 2 * ROWS) {
        float2* hb = (tid < ROWS) ? h0 : h1;
        hb[(tid & 63) * RS + 35] = make_float2(1.0f, 0.0f);
    }

    // ---- per-thread n-gate constants (column-only: shared across row halves) ----
    float wn0[4], wn1[4], wn2[4], bnn[4], bhn[4];
#pragma unroll
    for (int u = 0; u < 4; u++) {            // u = p*2 + q
        int j = cg * 16 + (u >> 1) * 8 + tg * 2 + (u & 1);
        int nr = 128 + j;
        wn0[u] = Wih[nr * 3 + 0]; wn1[u] = Wih[nr * 3 + 1]; wn2[u] = Wih[nr * 3 + 2];
        bnn[u] = bih[nr];         bhn[u]  = bhh[nr];
    }

    // ---- x stream: threads 0..191 each own one (row, component) ----
    const float* xp = nullptr;
    int xrow = 0, xc = 0;
    if (tid < 3 * ROWS) {
        xrow = tid / 3; xc = tid % 3;
        int rho = blockIdx.x * ROWS + xrow;
        xp = (rho < B_) ? (x1 + (size_t)rho * T_ * 3 + xc)
                        : (x2 + (size_t)(rho - B_) * T_ * 3 + xc);
        h0[xrow * RS + 32 + xc] = make_float2(tfr(__ldg(xp)), 0.0f);   // x(0)
        xp += 3;
    }

    float hold[2][4];    // [rs][p*2+q], full precision
#pragma unroll
    for (int rs = 0; rs < 2; rs++)
#pragma unroll
        for (int u = 0; u < 4; u++) hold[rs][u] = 0.0f;

    __syncthreads();

    for (int t = 0; t < T_; t++) {
        const float2* hs = (t & 1) ? h1 : h0;
        float2*       hn = (t & 1) ? h0 : h1;

        float xnext = 0.0f;
        if (tid < 3 * ROWS && t + 1 < T_) { xnext = __ldg(xp); xp += 3; }

        float acc[6][4];
#pragma unroll
        for (int i = 0; i < 6; i++)
#pragma unroll
            for (int c = 0; c < 4; c++) acc[i][c] = 0.0f;

        const float2* arow0 = hs + (rg * 16 + gid) * RS;
        const float2* arow1 = arow0 + 8 * RS;

#pragma unroll
        for (int kt = 0; kt < 9; kt++) {
            uint32_t bx[6], by[6];
#pragma unroll
            for (int ti = 0; ti < 6; ti++) {              // ti = gate*2 + p
                int n = (ti >> 1) * 64 + cg * 16 + (ti & 1) * 8 + gid;
                float2 bb = Bs[n * RS + kt * 4 + tg];
                bx[ti] = __float_as_uint(bb.x); by[ti] = __float_as_uint(bb.y);
            }
            float2 lo = arow0[kt * 4 + tg];
            float2 hi = arow1[kt * 4 + tg];
            uint32_t a0 = __float_as_uint(lo.x), a1 = __float_as_uint(hi.x);
            uint32_t a2 = __float_as_uint(lo.y), a3 = __float_as_uint(hi.y);
#pragma unroll
            for (int ti = 0; ti < 6; ti++)
                mma8(acc[ti], a0, a1, a2, a3, bx[ti], by[ti]);
        }

        // ---- gate epilogue (all three gates of a unit on this thread) ----
        const float* hsf = reinterpret_cast<const float*>(hs);
        float*       hnf = reinterpret_cast<float*>(hn);
        float xs[2][3];
#pragma unroll
        for (int rs = 0; rs < 2; rs++) {
            int rowl = rg * 16 + gid + rs * 8;
#pragma unroll
            for (int c = 0; c < 3; c++) xs[rs][c] = hsf[rowl * (2 * RS) + 64 + 2 * c];
        }
#pragma unroll
        for (int rs = 0; rs < 2; rs++) {
            int rowl = rg * 16 + gid + rs * 8;
#pragma unroll
            for (int u = 0; u < 4; u++) {
                int p = u >> 1, q = u & 1;
                int c = rs * 2 + q;
                float r  = sigm(acc[p][c]);              // x + both biases folded in
                float z  = sigm(acc[2 + p][c]);
                float hh = acc[4 + p][c] + bhn[u];       // h-dot + b_hh (n gate)
                float xn = fmaf(xs[rs][2], wn2[u],
                            fmaf(xs[rs][1], wn1[u],
                             fmaf(xs[rs][0], wn0[u], bnn[u])));
                float nn = tanh_a(fmaf(r, hh, xn));
                float hv = fmaf(z, hold[rs][u] - nn, nn);   // (1-z)n + z*h
                hold[rs][u] = hv;
                int j = cg * 16 + p * 8 + tg * 2 + q, jm = j & 7;
                hnf[rowl * (2 * RS) + (j >> 3) * 8 + (jm & 3) * 2 + (jm >> 2)] = tfr(hv);
            }
        }
        if (tid < 3 * ROWS && t + 1 < T_)
            hn[xrow * RS + 32 + xc] = make_float2(tfr(xnext), 0.0f);

        __syncthreads();   // separates this step's reads from next step's writes
    }

    // ---- final hidden states straight from registers ----
#pragma unroll
    for (int rs = 0; rs < 2; rs++) {
        int row = blockIdx.x * ROWS + rg * 16 + gid + rs * 8;
#pragma unroll
        for (int u = 0; u < 4; u++) {
            int j = cg * 16 + (u >> 1) * 8 + tg * 2 + (u & 1);
            g_hlast[(size_t)row * 64 + j] = hold[rs][u];
        }
    }
}

// ============================================================================
// Head: out[b] = sigmoid(W2 @ relu(W1 @ |h1-h2| + b1) + b2)
// ============================================================================
__global__ void head_kernel(const float* __restrict__ W1, const float* __restrict__ b1,
                            const float* __restrict__ W2, const float* __restrict__ b2,
                            float* __restrict__ out)
{
    __shared__ float w1s[32 * 65];
    __shared__ float diffs[64];

    const int b = blockIdx.x;
    const int l = threadIdx.x;

    for (int i = l; i < 32 * 64; i += 32) {
        int m = i >> 6, k = i & 63;
        w1s[m * 65 + k] = W1[i];
    }
    diffs[l]      = fabsf(g_hlast[b * 64 + l]      - g_hlast[(B_ + b) * 64 + l]);
    diffs[32 + l] = fabsf(g_hlast[b * 64 + 32 + l] - g_hlast[(B_ + b) * 64 + 32 + l]);
    __syncwarp();

    float acc = b1[l];
#pragma unroll
    for (int k = 0; k < 64; k++) acc = fmaf(w1s[l * 65 + k], diffs[k], acc);
    acc = fmaxf(acc, 0.0f) * W2[l];

#pragma unroll
    for (int o = 16; o > 0; o >>= 1) acc += __shfl_xor_sync(0xffffffffu, acc, o);
    if (l == 0) out[b] = sigm(acc + b2[0]);
}

// ============================================================================
extern "C" void kernel_launch(void* const* d_in, const int* in_sizes, int n_in,
                              void* d_out, int out_size)
{
    (void)in_sizes; (void)n_in; (void)out_size;
    const float* x1  = (const float*)d_in[0];
    const float* x2  = (const float*)d_in[1];
    const float* Wih = (const float*)d_in[2];
    const float* Whh = (const float*)d_in[3];
    const float* bih = (const float*)d_in[4];
    const float* bhh = (const float*)d_in[5];
    const float* W1  = (const float*)d_in[6];
    const float* b1  = (const float*)d_in[7];
    const float* W2  = (const float*)d_in[8];
    const float* b2  = (const float*)d_in[9];
    float* out = (float*)d_out;

    const int dyn_smem = (192 + 2 * ROWS) * RS * (int)sizeof(float2);  // 92160 B
    cudaFuncSetAttribute(gru_kernel, cudaFuncAttributeMaxDynamicSharedMemorySize, dyn_smem);

    gru_kernel<<<NCTA, 512, dyn_smem>>>(x1, x2, Wih, Whh, bih, bhh);
    head_kernel<<<B_, 32>>>(W1, b1, W2, b2, out);
}